// round 13
// baseline (speedup 1.0000x reference)
#include <cuda_runtime.h>

#define NN    2048
#define HALF  1024
#define F     128
#define LATD  64
#define ES    65536
#define KS    8

// ---------------- scratch (device globals) ----------------
// g_zbuf invariant: ZERO at entry (module-load zero-init; k_scan re-zeroes).
__device__ unsigned g_zbuf[HALF + NN];   // [0,1024) colsum f32, [1024,3072) cnt i32
__device__ float g_S[HALF * HALF];       // tf32-rounded sigmoid(my[r,c]) at [r*1024+c]
__device__ float g_dinv[NN];
__device__ int   g_ptr[NN + 1];
__device__ int   g_cur[NN];
__device__ int   g_csrc[ES];
__device__ float g_h[NN * F];
__device__ float g_hsd[NN * F];          // tf32-rounded, dinv-scaled agg input
__device__ float g_acc[NN * F];
__device__ float g_part[KS * HALF * F];  // dense-agg partials (plain stores)

// ---------------- helpers ----------------
__device__ __forceinline__ unsigned long long pk2(float lo, float hi) {
    unsigned long long r;
    asm("mov.b64 %0, {%1, %2};" : "=l"(r) : "f"(lo), "f"(hi));
    return r;
}
__device__ __forceinline__ float2 upk2(unsigned long long v) {
    float2 f;
    asm("mov.b64 {%0, %1}, %2;" : "=f"(f.x), "=f"(f.y) : "l"(v));
    return f;
}
__device__ __forceinline__ void fma2(unsigned long long& c,
                                     unsigned long long a, unsigned long long b) {
    asm("fma.rn.f32x2 %0, %1, %2, %3;" : "=l"(c) : "l"(a), "l"(b), "l"(c));
}
__device__ __forceinline__ float cvt_tf32(float v) {
    unsigned u;
    asm("cvt.rna.tf32.f32 %0, %1;" : "=r"(u) : "f"(v));
    return __uint_as_float(u);
}
__device__ __forceinline__ float fast_sigmoid(float x) {
    float t;
    asm("tanh.approx.f32 %0, %1;" : "=f"(t) : "f"(0.5f * x));
    return fmaf(0.5f, t, 0.5f);
}

// ================= mega kernel A: gemm1 | sigmoid+colsum | sparse count ======
__global__ void k_megaA(const float* __restrict__ my, const int* __restrict__ ei,
                        const float* __restrict__ x, const float* __restrict__ W1) {
    int b = blockIdx.x;
    int tid = threadIdx.x;
    if (b < 64) {
        __shared__ float As[16][65];
        __shared__ float Bs[16 * 64];
        int col0 = (b & 1) * 64;
        int row0 = (b >> 1) * 64;
        int tx = tid & 15, ty = tid >> 4;
        unsigned long long acc[4][2] = {};
        for (int k0 = 0; k0 < 128; k0 += 16) {
            for (int l = tid; l < 64 * 16; l += 256) {
                int i = l >> 4, kk = l & 15;
                As[kk][i] = x[(row0 + i) * 128 + k0 + kk];
            }
            for (int l = tid; l < 16 * 64; l += 256) {
                int kk = l >> 6, j = l & 63;
                Bs[kk * 64 + j] = W1[(k0 + kk) * 128 + col0 + j];
            }
            __syncthreads();
#pragma unroll
            for (int kk = 0; kk < 16; kk++) {
                unsigned long long ad[4], bb[2];
#pragma unroll
                for (int m = 0; m < 4; m++) { float a = As[kk][ty + m * 16]; ad[m] = pk2(a, a); }
                const float2* brow = (const float2*)(Bs + kk * 64);
#pragma unroll
                for (int n = 0; n < 2; n++) { float2 bv = brow[tx + n * 16]; bb[n] = pk2(bv.x, bv.y); }
#pragma unroll
                for (int m = 0; m < 4; m++)
#pragma unroll
                    for (int n = 0; n < 2; n++) fma2(acc[m][n], ad[m], bb[n]);
            }
            __syncthreads();
        }
        cudaTriggerProgrammaticLaunchCompletion();
#pragma unroll
        for (int m = 0; m < 4; m++) {
            int r = row0 + ty + m * 16;
#pragma unroll
            for (int n = 0; n < 2; n++) {
                float2 v = upk2(acc[m][n]);
                int cc = col0 + 2 * (tx + n * 16);
                g_h[r * 128 + cc]     = v.x;
                g_h[r * 128 + cc + 1] = v.y;
            }
        }
    } else if (b < 1088) {
        int t = b - 64;
        __shared__ float sm[256];
        int r0 = (t >> 5) * 32, c0 = (t & 31) * 32;
        int tx = tid & 31, ty = tid >> 5;
        int c = c0 + tx;
        float csum = 0.f;
#pragma unroll
        for (int rr = 0; rr < 4; rr++) {
            int r = r0 + ty + rr * 8;
            float v = cvt_tf32(fast_sigmoid(my[r * 2048 + c]));
            g_S[r * HALF + c] = v;
            csum += v;
        }
        sm[tid] = csum;
        __syncthreads();
        if (ty < 4) sm[tid] += sm[tid + 128];
        __syncthreads();
        if (ty < 2) sm[tid] += sm[tid + 64];
        __syncthreads();
        cudaTriggerProgrammaticLaunchCompletion();
        if (ty == 0) atomicAdd(&((float*)g_zbuf)[c], sm[tid] + sm[tid + 32]);
    } else {
        int e = (b - 1088) * 256 + tid;
        atomicAdd((int*)g_zbuf + HALF + ei[ES + e], 1);
        cudaTriggerProgrammaticLaunchCompletion();
    }
}

// ================= scan: CSR ptr + dinv; then re-zero g_zbuf =================
__global__ void k_scan() {
    cudaGridDependencySynchronize();
    const int* cnt = (const int*)g_zbuf + HALF;
    const float* colsum = (const float*)g_zbuf;
    int t = threadIdx.x;
    int a = cnt[2 * t], b2 = cnt[2 * t + 1];
    int s = a + b2;
    int lane = t & 31, w = t >> 5;
    int v = s;
#pragma unroll
    for (int off = 1; off < 32; off <<= 1) {
        int u = __shfl_up_sync(0xffffffffu, v, off);
        if (lane >= off) v += u;
    }
    __shared__ int wsum[32];
    if (lane == 31) wsum[w] = v;
    __syncthreads();
    if (w == 0) {
        int xx = wsum[lane];
#pragma unroll
        for (int off = 1; off < 32; off <<= 1) {
            int u = __shfl_up_sync(0xffffffffu, xx, off);
            if (lane >= off) xx += u;
        }
        wsum[lane] = xx;
    }
    __syncthreads();
    int base = (w > 0) ? wsum[w - 1] : 0;
    int excl = base + v - s;
    g_ptr[2 * t] = excl;       g_ptr[2 * t + 1] = excl + a;
    g_cur[2 * t] = excl;       g_cur[2 * t + 1] = excl + a;
    if (t == 1023) g_ptr[NN] = ES;
    float d0 = 1.0f + (float)a  + (2 * t     < HALF ? colsum[2 * t]     : 0.f);
    float d1 = 1.0f + (float)b2 + (2 * t + 1 < HALF ? colsum[2 * t + 1] : 0.f);
    g_dinv[2 * t]     = rsqrtf(d0);
    g_dinv[2 * t + 1] = rsqrtf(d1);
    __syncthreads();
    g_zbuf[t] = 0u; g_zbuf[t + 1024] = 0u; g_zbuf[t + 2048] = 0u;
}

// ================= CSR fill | hsd = tf32(dinv * h) (float4) ==================
__global__ void k_fill_scale(const int* __restrict__ ei) {
    int b = blockIdx.x, tid = threadIdx.x;
    cudaGridDependencySynchronize();
    if (b < 256) {
        int e = b * 256 + tid;
        int dst = ei[ES + e];
        int pos = atomicAdd(&g_cur[dst], 1);
        g_csrc[pos] = ei[e];
    } else {
        int idx = (b - 256) * 256 + tid;            // float4 index
        float d = g_dinv[idx >> 5];
        float4 a = ((const float4*)g_h)[idx];
        a.x = cvt_tf32(a.x * d); a.y = cvt_tf32(a.y * d);
        a.z = cvt_tf32(a.z * d); a.w = cvt_tf32(a.w * d);
        ((float4*)g_hsd)[idx] = a;
    }
    cudaTriggerProgrammaticLaunchCompletion();
}

// ================= fused aggregation: dense tf32 MMA | edge CSR =============
// blocks [0,128): dense 64c x 128f x 128k slab -> g_part (plain stores),
//                 register-prefetch pipelined staging, float4 LDG.
// blocks [128,2176): edge, 1 node per block, 8 warps = 8 edge-eighths
#define SAS 72    // sA row stride (floats): 64 data + 8 pad
#define SBS 136   // sB row stride (floats): 128 data + 8 pad
__global__ void __launch_bounds__(256) k_agg(const float* __restrict__ in) {
    __shared__ __align__(16) float sA[32 * SAS];
    __shared__ __align__(16) float sB[32 * SBS];
    int b = blockIdx.x;
    int tid = threadIdx.x;
    cudaGridDependencySynchronize();
    if (b < 128) {
        int c0 = (b & 15) * 64;
        int split = b >> 4;
        int kbase = split * 128;
        int wid = tid >> 5, lane = tid & 31;
        int wm = wid & 3, wn = wid >> 2;            // warp tile: 16m x 64n
        int g = lane >> 2, tg = lane & 3;
        float c[8][4] = {};
        float4 rA[2], rB[4];
        // prologue: prefetch kt=0
#pragma unroll
        for (int i = 0; i < 2; i++) {
            int v = i * 256 + tid;
            rA[i] = *(const float4*)&g_S[(kbase + (v >> 4)) * HALF + c0 + (v & 15) * 4];
        }
#pragma unroll
        for (int i = 0; i < 4; i++) {
            int v = i * 256 + tid;
            rB[i] = *(const float4*)&in[(kbase + (v >> 5)) * F + (v & 31) * 4];
        }
        for (int kt = 0; kt < 4; kt++) {
            __syncthreads();                        // prev compute done
#pragma unroll
            for (int i = 0; i < 2; i++) {
                int v = i * 256 + tid;
                *(float4*)&sA[(v >> 4) * SAS + (v & 15) * 4] = rA[i];
            }
#pragma unroll
            for (int i = 0; i < 4; i++) {
                int v = i * 256 + tid;
                *(float4*)&sB[(v >> 5) * SBS + (v & 31) * 4] = rB[i];
            }
            __syncthreads();
            if (kt < 3) {                           // prefetch next tile (hidden)
                int k0 = kbase + (kt + 1) * 32;
#pragma unroll
                for (int i = 0; i < 2; i++) {
                    int v = i * 256 + tid;
                    rA[i] = *(const float4*)&g_S[(k0 + (v >> 4)) * HALF + c0 + (v & 15) * 4];
                }
#pragma unroll
                for (int i = 0; i < 4; i++) {
                    int v = i * 256 + tid;
                    rB[i] = *(const float4*)&in[(k0 + (v >> 5)) * F + (v & 31) * 4];
                }
            }
#pragma unroll
            for (int ks = 0; ks < 4; ks++) {
                int kb = ks * 8;
                unsigned a0 = __float_as_uint(sA[(kb + tg) * SAS + wm * 16 + g]);
                unsigned a1 = __float_as_uint(sA[(kb + tg) * SAS + wm * 16 + g + 8]);
                unsigned a2 = __float_as_uint(sA[(kb + tg + 4) * SAS + wm * 16 + g]);
                unsigned a3 = __float_as_uint(sA[(kb + tg + 4) * SAS + wm * 16 + g + 8]);
#pragma unroll
                for (int nn = 0; nn < 8; nn++) {
                    int n0 = wn * 64 + nn * 8;
                    unsigned b0 = __float_as_uint(sB[(kb + tg) * SBS + n0 + g]);
                    unsigned b1 = __float_as_uint(sB[(kb + tg + 4) * SBS + n0 + g]);
                    asm("mma.sync.aligned.m16n8k8.row.col.f32.tf32.tf32.f32 "
                        "{%0,%1,%2,%3}, {%4,%5,%6,%7}, {%8,%9}, {%0,%1,%2,%3};"
                        : "+f"(c[nn][0]), "+f"(c[nn][1]), "+f"(c[nn][2]), "+f"(c[nn][3])
                        : "r"(a0), "r"(a1), "r"(a2), "r"(a3), "r"(b0), "r"(b1));
                }
            }
        }
        cudaTriggerProgrammaticLaunchCompletion();
        float* dst = g_part + split * HALF * F;
#pragma unroll
        for (int nn = 0; nn < 8; nn++) {
            int row = c0 + wm * 16 + g;
            int col = wn * 64 + nn * 8 + 2 * tg;
            dst[row * F + col]           = c[nn][0];
            dst[row * F + col + 1]       = c[nn][1];
            dst[(row + 8) * F + col]     = c[nn][2];
            dst[(row + 8) * F + col + 1] = c[nn][3];
        }
    } else {
        // edge: one node, 8 warps each take 1/8 of the edge list (~4 edges)
        float4* smE = (float4*)sA;                   // 7*32 float4 = 3.5 KB
        const float4* in4 = (const float4*)in;
        int node = b - 128;
        int wid = tid >> 5, lane = tid & 31;
        int p0 = g_ptr[node], p1 = g_ptr[node + 1];
        int len = p1 - p0;
        int p  = p0 + ((len * wid) >> 3);
        int pe = p0 + ((len * (wid + 1)) >> 3);
        float4 acc;
        if (wid == 0) acc = in4[node * 32 + lane];   // self loop (pre-scaled)
        else          acc = make_float4(0.f, 0.f, 0.f, 0.f);
        for (; p + 4 <= pe; p += 4) {
            int s0 = g_csrc[p], s1 = g_csrc[p + 1], s2 = g_csrc[p + 2], s3 = g_csrc[p + 3];
            float4 v0 = in4[s0 * 32 + lane], v1 = in4[s1 * 32 + lane];
            float4 v2 = in4[s2 * 32 + lane], v3 = in4[s3 * 32 + lane];
            acc.x += (v0.x + v1.x) + (v2.x + v3.x);
            acc.y += (v0.y + v1.y) + (v2.y + v3.y);
            acc.z += (v0.z + v1.z) + (v2.z + v3.z);
            acc.w += (v0.w + v1.w) + (v2.w + v3.w);
        }
        for (; p < pe; p++) {
            float4 v = in4[g_csrc[p] * 32 + lane];
            acc.x += v.x; acc.y += v.y; acc.z += v.z; acc.w += v.w;
        }
        if (wid != 0) smE[(wid - 1) * 32 + lane] = acc;
        __syncthreads();
        cudaTriggerProgrammaticLaunchCompletion();
        if (wid == 0) {
            float4 o0 = smE[0 * 32 + lane], o1 = smE[1 * 32 + lane];
            float4 o2 = smE[2 * 32 + lane], o3 = smE[3 * 32 + lane];
            float4 o4 = smE[4 * 32 + lane], o5 = smE[5 * 32 + lane];
            float4 o6 = smE[6 * 32 + lane];
            acc.x += ((o0.x + o1.x) + (o2.x + o3.x)) + ((o4.x + o5.x) + o6.x);
            acc.y += ((o0.y + o1.y) + (o2.y + o3.y)) + ((o4.y + o5.y) + o6.y);
            acc.z += ((o0.z + o1.z) + (o2.z + o3.z)) + ((o4.z + o5.z) + o6.z);
            acc.w += ((o0.w + o1.w) + (o2.w + o3.w)) + ((o4.w + o5.w) + o6.w);
            ((float4*)g_acc)[node * 32 + lane] = acc;  // plain store — inits acc
        }
    }
}

// ===== fin1: reduce partials; hsd = tf32(dinv*relu(dinv*acc+b1)) =============
__global__ void k_fin1(const float* __restrict__ b1) {
    int idx = blockIdx.x * 256 + threadIdx.x;       // float4 index (65536 total)
    cudaGridDependencySynchronize();
    float4 a = ((const float4*)g_acc)[idx];
    if (idx < HALF * F / 4) {
#pragma unroll
        for (int s = 0; s < KS; s++) {
            float4 pp = ((const float4*)g_part)[s * (HALF * F / 4) + idx];
            a.x += pp.x; a.y += pp.y; a.z += pp.z; a.w += pp.w;
        }
    }
    float d = g_dinv[idx >> 5];
    int cb = (idx & 31) * 4;
    float4 o;
    o.x = cvt_tf32(d * fmaxf(d * a.x + b1[cb],     0.f));
    o.y = cvt_tf32(d * fmaxf(d * a.y + b1[cb + 1], 0.f));
    o.z = cvt_tf32(d * fmaxf(d * a.z + b1[cb + 2], 0.f));
    o.w = cvt_tf32(d * fmaxf(d * a.w + b1[cb + 3], 0.f));
    ((float4*)g_hsd)[idx] = o;
    cudaTriggerProgrammaticLaunchCompletion();
}

// ================= output: [z_mu|z_logstd] = dinv*(acc+Σpart) @ [Wmu|Wls] ====
__global__ void __launch_bounds__(256) k_out(
        const float* __restrict__ Wmu, const float* __restrict__ bmu,
        const float* __restrict__ Wls, const float* __restrict__ bls,
        float* __restrict__ out) {
    __shared__ float As[16][33];
    __shared__ float Bs[16 * 128];
    int row0 = blockIdx.x * 32;
    bool firsthalf = row0 < HALF;
    int tid = threadIdx.x;
    int tx = tid & 15, ty = tid >> 4;
    cudaGridDependencySynchronize();
    unsigned long long acc[2][4] = {};
    for (int k0 = 0; k0 < 128; k0 += 16) {
        for (int l = tid; l < 32 * 16; l += 256) {
            int i = l >> 4, kk = l & 15;
            int r = row0 + i;
            float v = g_acc[r * F + k0 + kk];
            if (firsthalf) {
#pragma unroll
                for (int s = 0; s < KS; s++) v += g_part[s * HALF * F + r * F + k0 + kk];
            }
            As[kk][i] = v * g_dinv[r];
        }
        for (int l = tid; l < 16 * 128; l += 256) {
            int kk = l >> 7, j = l & 127;
            Bs[kk * 128 + j] = (j < 64) ? Wmu[(k0 + kk) * LATD + j]
                                        : Wls[(k0 + kk) * LATD + (j - 64)];
        }
        __syncthreads();
#pragma unroll
        for (int kk = 0; kk < 16; kk++) {
            unsigned long long ad[2], bb[4];
#pragma unroll
            for (int m = 0; m < 2; m++) { float a = As[kk][ty + m * 16]; ad[m] = pk2(a, a); }
            const float2* brow = (const float2*)(Bs + kk * 128);
#pragma unroll
            for (int n = 0; n < 4; n++) { float2 bv = brow[tx + n * 16]; bb[n] = pk2(bv.x, bv.y); }
#pragma unroll
            for (int m = 0; m < 2; m++)
#pragma unroll
                for (int n = 0; n < 4; n++) fma2(acc[m][n], ad[m], bb[n]);
        }
        __syncthreads();
    }
#pragma unroll
    for (int m = 0; m < 2; m++) {
        int r = row0 + ty + m * 16;
#pragma unroll
        for (int n = 0; n < 4; n++) {
            float2 v = upk2(acc[m][n]);
            int j = 2 * (tx + n * 16);              // pairs never cross 64
            if (j < 64) {
                out[r * LATD + j]     = v.x + bmu[j];
                out[r * LATD + j + 1] = v.y + bmu[j + 1];
            } else {
                int jj = j - 64;
                out[NN * LATD + r * LATD + jj]     = v.x + bls[jj];
                out[NN * LATD + r * LATD + jj + 1] = v.y + bls[jj + 1];
            }
        }
    }
}

// ---------------- PDL launch helper ----------------
template <typename... Args>
static void launch_pdl(void (*kern)(Args...), dim3 grid, dim3 block, Args... args) {
    cudaLaunchConfig_t cfg = {};
    cfg.gridDim = grid;
    cfg.blockDim = block;
    cfg.dynamicSmemBytes = 0;
    cfg.stream = 0;
    cudaLaunchAttribute attr[1];
    attr[0].id = cudaLaunchAttributeProgrammaticStreamSerialization;
    attr[0].val.programmaticStreamSerializationAllowed = 1;
    cfg.attrs = attr;
    cfg.numAttrs = 1;
    cudaLaunchKernelEx(&cfg, kern, args...);
}

// ================= launch: 7 nodes, PDL-chained ==============================
extern "C" void kernel_launch(void* const* d_in, const int* in_sizes, int n_in,
                              void* d_out, int out_size) {
    const float* x   = (const float*)d_in[0];
    const float* my  = (const float*)d_in[1];
    const float* W1  = (const float*)d_in[2];
    const float* b1  = (const float*)d_in[3];
    const float* Wmu = (const float*)d_in[4];
    const float* bmu = (const float*)d_in[5];
    const float* Wls = (const float*)d_in[6];
    const float* bls = (const float*)d_in[7];
    const int*   ei  = (const int*)d_in[8];
    float* out = (float*)d_out;

    void* p_hsd;
    cudaGetSymbolAddress(&p_hsd, g_hsd);
    const float* hsd = (const float*)p_hsd;

    k_megaA<<<1344, 256>>>(my, ei, x, W1);
    launch_pdl(k_scan, dim3(1), dim3(1024));
    launch_pdl(k_fill_scale, dim3(512), dim3(256), ei);

    launch_pdl(k_agg, dim3(2176), dim3(256), hsd);   // pass 1
    launch_pdl(k_fin1, dim3(256), dim3(256), b1);
    launch_pdl(k_agg, dim3(2176), dim3(256), hsd);   // pass 2

    launch_pdl(k_out, dim3(64), dim3(256), Wmu, bmu, Wls, bls, out);
}

// round 14
// speedup vs baseline: 1.0931x; 1.0931x over previous
#include <cuda_runtime.h>

#define NN    2048
#define HALF  1024
#define F     128
#define LATD  64
#define ES    65536
#define KS    8

// ---------------- scratch (device globals) ----------------
// g_zbuf invariant: ZERO at entry (module-load zero-init; k_scan re-zeroes).
__device__ unsigned g_zbuf[HALF + NN];   // [0,1024) colsum f32, [1024,3072) cnt i32
__device__ float g_S[HALF * HALF];       // tf32-rounded sigmoid(my[r,c]) at [r*1024+c]
__device__ float g_dinv[NN];
__device__ int   g_ptr[NN + 1];
__device__ int   g_cur[NN];
__device__ int   g_csrc[ES];
__device__ float g_h[NN * F];
__device__ float g_hsd[NN * F];          // tf32-rounded, dinv-scaled agg input
__device__ float g_acc[NN * F];
__device__ float g_part[KS * HALF * F];  // dense-agg partials (plain stores)

// ---------------- helpers ----------------
__device__ __forceinline__ unsigned long long pk2(float lo, float hi) {
    unsigned long long r;
    asm("mov.b64 %0, {%1, %2};" : "=l"(r) : "f"(lo), "f"(hi));
    return r;
}
__device__ __forceinline__ float2 upk2(unsigned long long v) {
    float2 f;
    asm("mov.b64 {%0, %1}, %2;" : "=f"(f.x), "=f"(f.y) : "l"(v));
    return f;
}
__device__ __forceinline__ void fma2(unsigned long long& c,
                                     unsigned long long a, unsigned long long b) {
    asm("fma.rn.f32x2 %0, %1, %2, %3;" : "=l"(c) : "l"(a), "l"(b), "l"(c));
}
__device__ __forceinline__ float cvt_tf32(float v) {
    unsigned u;
    asm("cvt.rna.tf32.f32 %0, %1;" : "=r"(u) : "f"(v));
    return __uint_as_float(u);
}
__device__ __forceinline__ float fast_sigmoid(float x) {
    float t;
    asm("tanh.approx.f32 %0, %1;" : "=f"(t) : "f"(0.5f * x));
    return fmaf(0.5f, t, 0.5f);
}

// ================= mega kernel A: gemm1 | sigmoid+colsum | sparse count ======
__global__ void k_megaA(const float* __restrict__ my, const int* __restrict__ ei,
                        const float* __restrict__ x, const float* __restrict__ W1) {
    int b = blockIdx.x;
    int tid = threadIdx.x;
    if (b < 64) {
        __shared__ float As[16][65];
        __shared__ float Bs[16 * 64];
        int col0 = (b & 1) * 64;
        int row0 = (b >> 1) * 64;
        int tx = tid & 15, ty = tid >> 4;
        unsigned long long acc[4][2] = {};
        for (int k0 = 0; k0 < 128; k0 += 16) {
            for (int l = tid; l < 64 * 16; l += 256) {
                int i = l >> 4, kk = l & 15;
                As[kk][i] = x[(row0 + i) * 128 + k0 + kk];
            }
            for (int l = tid; l < 16 * 64; l += 256) {
                int kk = l >> 6, j = l & 63;
                Bs[kk * 64 + j] = W1[(k0 + kk) * 128 + col0 + j];
            }
            __syncthreads();
#pragma unroll
            for (int kk = 0; kk < 16; kk++) {
                unsigned long long ad[4], bb[2];
#pragma unroll
                for (int m = 0; m < 4; m++) { float a = As[kk][ty + m * 16]; ad[m] = pk2(a, a); }
                const float2* brow = (const float2*)(Bs + kk * 64);
#pragma unroll
                for (int n = 0; n < 2; n++) { float2 bv = brow[tx + n * 16]; bb[n] = pk2(bv.x, bv.y); }
#pragma unroll
                for (int m = 0; m < 4; m++)
#pragma unroll
                    for (int n = 0; n < 2; n++) fma2(acc[m][n], ad[m], bb[n]);
            }
            __syncthreads();
        }
        cudaTriggerProgrammaticLaunchCompletion();
#pragma unroll
        for (int m = 0; m < 4; m++) {
            int r = row0 + ty + m * 16;
#pragma unroll
            for (int n = 0; n < 2; n++) {
                float2 v = upk2(acc[m][n]);
                int cc = col0 + 2 * (tx + n * 16);
                g_h[r * 128 + cc]     = v.x;
                g_h[r * 128 + cc + 1] = v.y;
            }
        }
    } else if (b < 1088) {
        int t = b - 64;
        __shared__ float sm[256];
        int r0 = (t >> 5) * 32, c0 = (t & 31) * 32;
        int tx = tid & 31, ty = tid >> 5;
        int c = c0 + tx;
        float csum = 0.f;
#pragma unroll
        for (int rr = 0; rr < 4; rr++) {
            int r = r0 + ty + rr * 8;
            float v = cvt_tf32(fast_sigmoid(my[r * 2048 + c]));
            g_S[r * HALF + c] = v;
            csum += v;
        }
        sm[tid] = csum;
        __syncthreads();
        if (ty < 4) sm[tid] += sm[tid + 128];
        __syncthreads();
        if (ty < 2) sm[tid] += sm[tid + 64];
        __syncthreads();
        cudaTriggerProgrammaticLaunchCompletion();
        if (ty == 0) atomicAdd(&((float*)g_zbuf)[c], sm[tid] + sm[tid + 32]);
    } else {
        int e = (b - 1088) * 256 + tid;
        atomicAdd((int*)g_zbuf + HALF + ei[ES + e], 1);
        cudaTriggerProgrammaticLaunchCompletion();
    }
}

// ================= scan: CSR ptr + dinv; then re-zero g_zbuf =================
__global__ void k_scan() {
    cudaGridDependencySynchronize();
    const int* cnt = (const int*)g_zbuf + HALF;
    const float* colsum = (const float*)g_zbuf;
    int t = threadIdx.x;
    int a = cnt[2 * t], b2 = cnt[2 * t + 1];
    int s = a + b2;
    int lane = t & 31, w = t >> 5;
    int v = s;
#pragma unroll
    for (int off = 1; off < 32; off <<= 1) {
        int u = __shfl_up_sync(0xffffffffu, v, off);
        if (lane >= off) v += u;
    }
    __shared__ int wsum[32];
    if (lane == 31) wsum[w] = v;
    __syncthreads();
    if (w == 0) {
        int xx = wsum[lane];
#pragma unroll
        for (int off = 1; off < 32; off <<= 1) {
            int u = __shfl_up_sync(0xffffffffu, xx, off);
            if (lane >= off) xx += u;
        }
        wsum[lane] = xx;
    }
    __syncthreads();
    int base = (w > 0) ? wsum[w - 1] : 0;
    int excl = base + v - s;
    g_ptr[2 * t] = excl;       g_ptr[2 * t + 1] = excl + a;
    g_cur[2 * t] = excl;       g_cur[2 * t + 1] = excl + a;
    if (t == 1023) g_ptr[NN] = ES;
    float d0 = 1.0f + (float)a  + (2 * t     < HALF ? colsum[2 * t]     : 0.f);
    float d1 = 1.0f + (float)b2 + (2 * t + 1 < HALF ? colsum[2 * t + 1] : 0.f);
    g_dinv[2 * t]     = rsqrtf(d0);
    g_dinv[2 * t + 1] = rsqrtf(d1);
    __syncthreads();
    g_zbuf[t] = 0u; g_zbuf[t + 1024] = 0u; g_zbuf[t + 2048] = 0u;
}

// ================= CSR fill | hsd = tf32(dinv * h) (float4) ==================
__global__ void k_fill_scale(const int* __restrict__ ei) {
    int b = blockIdx.x, tid = threadIdx.x;
    cudaGridDependencySynchronize();
    if (b < 256) {
        int e = b * 256 + tid;
        int dst = ei[ES + e];
        int pos = atomicAdd(&g_cur[dst], 1);
        g_csrc[pos] = ei[e];
    } else {
        int idx = (b - 256) * 256 + tid;            // float4 index
        float d = g_dinv[idx >> 5];
        float4 a = ((const float4*)g_h)[idx];
        a.x = cvt_tf32(a.x * d); a.y = cvt_tf32(a.y * d);
        a.z = cvt_tf32(a.z * d); a.w = cvt_tf32(a.w * d);
        ((float4*)g_hsd)[idx] = a;
    }
    cudaTriggerProgrammaticLaunchCompletion();
}

// ================= dense aggregation: 64c x 128f x 128k, pipelined ==========
// 128 blocks (< 148 SMs -> 1 block/SM, occupancy irrelevant). regs ~94 OK.
#define SAS 72    // sA row stride (floats)
#define SBS 136   // sB row stride (floats)
__global__ void __launch_bounds__(256) k_agg_dense(const float* __restrict__ in) {
    __shared__ __align__(16) float sA[32 * SAS];
    __shared__ __align__(16) float sB[32 * SBS];
    int b = blockIdx.x;
    int tid = threadIdx.x;
    cudaGridDependencySynchronize();
    int c0 = (b & 15) * 64;
    int split = b >> 4;
    int kbase = split * 128;
    int wid = tid >> 5, lane = tid & 31;
    int wm = wid & 3, wn = wid >> 2;                // warp tile: 16m x 64n
    int g = lane >> 2, tg = lane & 3;
    float c[8][4] = {};
    float4 rA[2], rB[4];
#pragma unroll
    for (int i = 0; i < 2; i++) {
        int v = i * 256 + tid;
        rA[i] = *(const float4*)&g_S[(kbase + (v >> 4)) * HALF + c0 + (v & 15) * 4];
    }
#pragma unroll
    for (int i = 0; i < 4; i++) {
        int v = i * 256 + tid;
        rB[i] = *(const float4*)&in[(kbase + (v >> 5)) * F + (v & 31) * 4];
    }
    for (int kt = 0; kt < 4; kt++) {
        __syncthreads();
#pragma unroll
        for (int i = 0; i < 2; i++) {
            int v = i * 256 + tid;
            *(float4*)&sA[(v >> 4) * SAS + (v & 15) * 4] = rA[i];
        }
#pragma unroll
        for (int i = 0; i < 4; i++) {
            int v = i * 256 + tid;
            *(float4*)&sB[(v >> 5) * SBS + (v & 31) * 4] = rB[i];
        }
        __syncthreads();
        if (kt < 3) {
            int k0 = kbase + (kt + 1) * 32;
#pragma unroll
            for (int i = 0; i < 2; i++) {
                int v = i * 256 + tid;
                rA[i] = *(const float4*)&g_S[(k0 + (v >> 4)) * HALF + c0 + (v & 15) * 4];
            }
#pragma unroll
            for (int i = 0; i < 4; i++) {
                int v = i * 256 + tid;
                rB[i] = *(const float4*)&in[(k0 + (v >> 5)) * F + (v & 31) * 4];
            }
        }
#pragma unroll
        for (int ks = 0; ks < 4; ks++) {
            int kb = ks * 8;
            unsigned a0 = __float_as_uint(sA[(kb + tg) * SAS + wm * 16 + g]);
            unsigned a1 = __float_as_uint(sA[(kb + tg) * SAS + wm * 16 + g + 8]);
            unsigned a2 = __float_as_uint(sA[(kb + tg + 4) * SAS + wm * 16 + g]);
            unsigned a3 = __float_as_uint(sA[(kb + tg + 4) * SAS + wm * 16 + g + 8]);
#pragma unroll
            for (int nn = 0; nn < 8; nn++) {
                int n0 = wn * 64 + nn * 8;
                unsigned b0 = __float_as_uint(sB[(kb + tg) * SBS + n0 + g]);
                unsigned b1 = __float_as_uint(sB[(kb + tg + 4) * SBS + n0 + g]);
                asm("mma.sync.aligned.m16n8k8.row.col.f32.tf32.tf32.f32 "
                    "{%0,%1,%2,%3}, {%4,%5,%6,%7}, {%8,%9}, {%0,%1,%2,%3};"
                    : "+f"(c[nn][0]), "+f"(c[nn][1]), "+f"(c[nn][2]), "+f"(c[nn][3])
                    : "r"(a0), "r"(a1), "r"(a2), "r"(a3), "r"(b0), "r"(b1));
            }
        }
    }
    cudaTriggerProgrammaticLaunchCompletion();
    float* dst = g_part + split * HALF * F;
#pragma unroll
    for (int nn = 0; nn < 8; nn++) {
        int row = c0 + wm * 16 + g;
        int col = wn * 64 + nn * 8 + 2 * tg;
        dst[row * F + col]           = c[nn][0];
        dst[row * F + col + 1]       = c[nn][1];
        dst[(row + 8) * F + col]     = c[nn][2];
        dst[(row + 8) * F + col + 1] = c[nn][3];
    }
}

// ================= edge + self-loop aggregation (lean, high-occ) =============
// 1 node per block, 8 warps = 8 edge-eighths, float4 per lane.
__global__ void __launch_bounds__(256) k_agg_edge(const float* __restrict__ in) {
    __shared__ float4 smE[7 * 32];
    cudaGridDependencySynchronize();
    const float4* in4 = (const float4*)in;
    int node = blockIdx.x;
    int tid = threadIdx.x;
    int wid = tid >> 5, lane = tid & 31;
    int p0 = g_ptr[node], p1 = g_ptr[node + 1];
    int len = p1 - p0;
    int p  = p0 + ((len * wid) >> 3);
    int pe = p0 + ((len * (wid + 1)) >> 3);
    float4 acc;
    if (wid == 0) acc = in4[node * 32 + lane];       // self loop (pre-scaled)
    else          acc = make_float4(0.f, 0.f, 0.f, 0.f);
    for (; p + 4 <= pe; p += 4) {
        int s0 = g_csrc[p], s1 = g_csrc[p + 1], s2 = g_csrc[p + 2], s3 = g_csrc[p + 3];
        float4 v0 = in4[s0 * 32 + lane], v1 = in4[s1 * 32 + lane];
        float4 v2 = in4[s2 * 32 + lane], v3 = in4[s3 * 32 + lane];
        acc.x += (v0.x + v1.x) + (v2.x + v3.x);
        acc.y += (v0.y + v1.y) + (v2.y + v3.y);
        acc.z += (v0.z + v1.z) + (v2.z + v3.z);
        acc.w += (v0.w + v1.w) + (v2.w + v3.w);
    }
    for (; p < pe; p++) {
        float4 v = in4[g_csrc[p] * 32 + lane];
        acc.x += v.x; acc.y += v.y; acc.z += v.z; acc.w += v.w;
    }
    if (wid != 0) smE[(wid - 1) * 32 + lane] = acc;
    __syncthreads();
    cudaTriggerProgrammaticLaunchCompletion();
    if (wid == 0) {
        float4 o0 = smE[0 * 32 + lane], o1 = smE[1 * 32 + lane];
        float4 o2 = smE[2 * 32 + lane], o3 = smE[3 * 32 + lane];
        float4 o4 = smE[4 * 32 + lane], o5 = smE[5 * 32 + lane];
        float4 o6 = smE[6 * 32 + lane];
        acc.x += ((o0.x + o1.x) + (o2.x + o3.x)) + ((o4.x + o5.x) + o6.x);
        acc.y += ((o0.y + o1.y) + (o2.y + o3.y)) + ((o4.y + o5.y) + o6.y);
        acc.z += ((o0.z + o1.z) + (o2.z + o3.z)) + ((o4.z + o5.z) + o6.z);
        acc.w += ((o0.w + o1.w) + (o2.w + o3.w)) + ((o4.w + o5.w) + o6.w);
        ((float4*)g_acc)[node * 32 + lane] = acc;    // plain store — inits acc
    }
}

// ===== fin1: reduce partials; hsd = tf32(dinv*relu(dinv*acc+b1)) =============
__global__ void k_fin1(const float* __restrict__ b1) {
    int idx = blockIdx.x * 256 + threadIdx.x;       // float4 index (65536 total)
    cudaGridDependencySynchronize();
    float4 a = ((const float4*)g_acc)[idx];
    if (idx < HALF * F / 4) {
#pragma unroll
        for (int s = 0; s < KS; s++) {
            float4 pp = ((const float4*)g_part)[s * (HALF * F / 4) + idx];
            a.x += pp.x; a.y += pp.y; a.z += pp.z; a.w += pp.w;
        }
    }
    float d = g_dinv[idx >> 5];
    int cb = (idx & 31) * 4;
    float4 o;
    o.x = cvt_tf32(d * fmaxf(d * a.x + b1[cb],     0.f));
    o.y = cvt_tf32(d * fmaxf(d * a.y + b1[cb + 1], 0.f));
    o.z = cvt_tf32(d * fmaxf(d * a.z + b1[cb + 2], 0.f));
    o.w = cvt_tf32(d * fmaxf(d * a.w + b1[cb + 3], 0.f));
    ((float4*)g_hsd)[idx] = o;
    cudaTriggerProgrammaticLaunchCompletion();
}

// ================= output: [z_mu|z_logstd] = dinv*(acc+Σpart) @ [Wmu|Wls] ====
__global__ void __launch_bounds__(256) k_out(
        const float* __restrict__ Wmu, const float* __restrict__ bmu,
        const float* __restrict__ Wls, const float* __restrict__ bls,
        float* __restrict__ out) {
    __shared__ float As[16][33];
    __shared__ float Bs[16 * 128];
    int row0 = blockIdx.x * 32;
    bool firsthalf = row0 < HALF;
    int tid = threadIdx.x;
    int tx = tid & 15, ty = tid >> 4;
    cudaGridDependencySynchronize();
    unsigned long long acc[2][4] = {};
    for (int k0 = 0; k0 < 128; k0 += 16) {
        for (int l = tid; l < 32 * 16; l += 256) {
            int i = l >> 4, kk = l & 15;
            int r = row0 + i;
            float v = g_acc[r * F + k0 + kk];
            if (firsthalf) {
#pragma unroll
                for (int s = 0; s < KS; s++) v += g_part[s * HALF * F + r * F + k0 + kk];
            }
            As[kk][i] = v * g_dinv[r];
        }
        for (int l = tid; l < 16 * 128; l += 256) {
            int kk = l >> 7, j = l & 127;
            Bs[kk * 128 + j] = (j < 64) ? Wmu[(k0 + kk) * LATD + j]
                                        : Wls[(k0 + kk) * LATD + (j - 64)];
        }
        __syncthreads();
#pragma unroll
        for (int kk = 0; kk < 16; kk++) {
            unsigned long long ad[2], bb[4];
#pragma unroll
            for (int m = 0; m < 2; m++) { float a = As[kk][ty + m * 16]; ad[m] = pk2(a, a); }
            const float2* brow = (const float2*)(Bs + kk * 128);
#pragma unroll
            for (int n = 0; n < 4; n++) { float2 bv = brow[tx + n * 16]; bb[n] = pk2(bv.x, bv.y); }
#pragma unroll
            for (int m = 0; m < 2; m++)
#pragma unroll
                for (int n = 0; n < 4; n++) fma2(acc[m][n], ad[m], bb[n]);
        }
        __syncthreads();
    }
#pragma unroll
    for (int m = 0; m < 2; m++) {
        int r = row0 + ty + m * 16;
#pragma unroll
        for (int n = 0; n < 4; n++) {
            float2 v = upk2(acc[m][n]);
            int j = 2 * (tx + n * 16);              // pairs never cross 64
            if (j < 64) {
                out[r * LATD + j]     = v.x + bmu[j];
                out[r * LATD + j + 1] = v.y + bmu[j + 1];
            } else {
                int jj = j - 64;
                out[NN * LATD + r * LATD + jj]     = v.x + bls[jj];
                out[NN * LATD + r * LATD + jj + 1] = v.y + bls[jj + 1];
            }
        }
    }
}

// ---------------- PDL launch helper ----------------
template <typename... Args>
static void launch_pdl(void (*kern)(Args...), dim3 grid, dim3 block, Args... args) {
    cudaLaunchConfig_t cfg = {};
    cfg.gridDim = grid;
    cfg.blockDim = block;
    cfg.dynamicSmemBytes = 0;
    cfg.stream = 0;
    cudaLaunchAttribute attr[1];
    attr[0].id = cudaLaunchAttributeProgrammaticStreamSerialization;
    attr[0].val.programmaticStreamSerializationAllowed = 1;
    cfg.attrs = attr;
    cfg.numAttrs = 1;
    cudaLaunchKernelEx(&cfg, kern, args...);
}

// ================= launch: 9 nodes, PDL-chained ==============================
extern "C" void kernel_launch(void* const* d_in, const int* in_sizes, int n_in,
                              void* d_out, int out_size) {
    const float* x   = (const float*)d_in[0];
    const float* my  = (const float*)d_in[1];
    const float* W1  = (const float*)d_in[2];
    const float* b1  = (const float*)d_in[3];
    const float* Wmu = (const float*)d_in[4];
    const float* bmu = (const float*)d_in[5];
    const float* Wls = (const float*)d_in[6];
    const float* bls = (const float*)d_in[7];
    const int*   ei  = (const int*)d_in[8];
    float* out = (float*)d_out;

    void* p_hsd;
    cudaGetSymbolAddress(&p_hsd, g_hsd);
    const float* hsd = (const float*)p_hsd;

    k_megaA<<<1344, 256>>>(my, ei, x, W1);
    launch_pdl(k_scan, dim3(1), dim3(1024));
    launch_pdl(k_fill_scale, dim3(512), dim3(256), ei);

    // pass 1
    launch_pdl(k_agg_dense, dim3(128), dim3(256), hsd);
    launch_pdl(k_agg_edge,  dim3(NN), dim3(256), hsd);
    launch_pdl(k_fin1, dim3(256), dim3(256), b1);

    // pass 2
    launch_pdl(k_agg_dense, dim3(128), dim3(256), hsd);
    launch_pdl(k_agg_edge,  dim3(NN), dim3(256), hsd);

    launch_pdl(k_out, dim3(64), dim3(256), Wmu, bmu, Wls, bls, out);
}